// round 14
// baseline (speedup 1.0000x reference)
#include <cuda_runtime.h>
#include <stdint.h>

#define B       8
#define NH      778
#define VOBJ    40000
#define NTOT    (B * NH)          // 6224
#define GD      32                // grid cells per axis
#define NC      (GD * GD * GD)    // 32768 cells per batch
#define CS      (0.1f / GD)       // cell size
#define INVCS   (GD / 0.1f)

#define QBLK    128
#define QGX     7                 // 7*128 = 896 >= 778
#define NQB     (QGX * B)         // 56 query blocks

__constant__ int c_contact_idx[10] = {745, 317, 444, 556, 673, 95, 182, 234, 279, 320};

// zero-initialized at load; scan_kernel re-zeros g_cnt each run -> replay-safe
__device__ int    g_cnt[B * NC];
__device__ int    g_start[B * (NC + 1)];   // CSR starts + sentinel per batch
__device__ int    g_fill[B * NC];          // scatter cursors (rewritten by scan)
__device__ int    g_cellid[B * VOBJ];
__device__ float4 g_pts[B * VOBJ];         // cell-sorted points
__device__ float  g_red_f[NQB * 3];
__device__ int    g_red_i[NQB * 2];
__device__ int    g_ticket;                // finalizer resets to 0

__device__ __forceinline__ void cell_of(float x, float y, float z,
                                        int& cx, int& cy, int& cz) {
    cx = min(GD - 1, max(0, (int)(x * INVCS)));
    cy = min(GD - 1, max(0, (int)(y * INVCS)));
    cz = min(GD - 1, max(0, (int)(z * INVCS)));
}

// K1: histogram points into cells (g_cnt zeroed by previous scan / initial load)
__global__ __launch_bounds__(256) void count_kernel(const float* __restrict__ obj)
{
    const int j = blockIdx.x * 256 + threadIdx.x;
    const int b = blockIdx.y;
    if (j >= VOBJ) return;
    const float* p = obj + ((size_t)b * VOBJ + j) * 3;
    int cx, cy, cz;
    cell_of(p[0], p[1], p[2], cx, cy, cz);
    const int cell = (cz * GD + cy) * GD + cx;
    g_cellid[b * VOBJ + j] = cell;
    atomicAdd(&g_cnt[b * NC + cell], 1);
}

// K2: exact exclusive prefix sum over 32768 cells per batch (1 block/batch),
// re-zeros g_cnt for the next replay, initializes g_fill = g_start.
__global__ __launch_bounds__(1024) void scan_kernel()
{
    const int b = blockIdx.x;
    const int t = threadIdx.x;
    const int lane = t & 31, wid = t >> 5;

    int c[32];
    int sum = 0;
    const int base = b * NC + t * 32;
    #pragma unroll
    for (int i = 0; i < 32; i++) {
        c[i] = g_cnt[base + i];
        g_cnt[base + i] = 0;          // reset for next run
        sum += c[i];
    }

    // warp inclusive scan of per-thread sums
    int incl = sum;
    #pragma unroll
    for (int off = 1; off < 32; off <<= 1) {
        int v = __shfl_up_sync(0xffffffffu, incl, off);
        if (lane >= off) incl += v;
    }
    __shared__ int wsum[32];
    if (lane == 31) wsum[wid] = incl;
    __syncthreads();
    if (wid == 0) {
        int v = wsum[lane];
        int wincl = v;
        #pragma unroll
        for (int off = 1; off < 32; off <<= 1) {
            int u = __shfl_up_sync(0xffffffffu, wincl, off);
            if (lane >= off) wincl += u;
        }
        wsum[lane] = wincl - v;       // exclusive
    }
    __syncthreads();

    int run = wsum[wid] + (incl - sum);   // exclusive prefix of this chunk
    const int sbase = b * (NC + 1) + t * 32;
    #pragma unroll
    for (int i = 0; i < 32; i++) {
        g_start[sbase + i] = run;
        g_fill[base + i]   = run;
        run += c[i];
    }
    if (t == 1023) g_start[b * (NC + 1) + NC] = run;   // == VOBJ
}

// K3: scatter points into cell-sorted order
__global__ __launch_bounds__(256) void scatter_kernel(const float* __restrict__ obj)
{
    const int j = blockIdx.x * 256 + threadIdx.x;
    const int b = blockIdx.y;
    if (j >= VOBJ) return;
    const float* p = obj + ((size_t)b * VOBJ + j) * 3;
    const int cell = g_cellid[b * VOBJ + j];
    const int pos  = atomicAdd(&g_fill[b * NC + cell], 1);
    g_pts[b * VOBJ + pos] = make_float4(p[0], p[1], p[2], 0.f);
}

// K4: exact 1-NN per hand vertex via expanding cube search + fused stats
__global__ __launch_bounds__(QBLK) void query_kernel(
    const float* __restrict__ hand, float* __restrict__ out)
{
    const int b = blockIdx.y;
    const int h = blockIdx.x * QBLK + threadIdx.x;
    const int t = threadIdx.x;

    float sum_d = 0.f, pen_sum = 0.f, att_sum = 0.f;
    int   pen_cnt = 0, att_cnt = 0;

    if (h < NH) {
        const float* hp = hand + ((size_t)b * NH + h) * 3;
        const float px = hp[0], py = hp[1], pz = hp[2];
        int cx, cy, cz;
        cell_of(px, py, pz, cx, cy, cz);
        const int sb = b * (NC + 1);
        const float4* pts = g_pts + (size_t)b * VOBJ;

        float best = 3.4e38f;
        for (int r = 1; r <= GD; r++) {
            const int x0 = max(0, cx - r), x1 = min(GD - 1, cx + r);
            const int y0 = max(0, cy - r), y1 = min(GD - 1, cy + r);
            const int z0 = max(0, cz - r), z1 = min(GD - 1, cz + r);
            best = 3.4e38f;
            for (int zz = z0; zz <= z1; zz++) {
                for (int yy = y0; yy <= y1; yy++) {
                    const int row = sb + (zz * GD + yy) * GD;
                    const int s = g_start[row + x0];
                    const int e = g_start[row + x1 + 1];   // contiguous x-run
                    for (int k = s; k < e; k++) {
                        float4 q = pts[k];
                        float dx = px - q.x, dy = py - q.y, dz = pz - q.z;
                        float d2 = fmaf(dx, dx, fmaf(dy, dy, dz * dz));
                        best = fminf(best, d2);
                    }
                }
            }
            const bool all = (x0 == 0) && (x1 == GD - 1) && (y0 == 0) &&
                             (y1 == GD - 1) && (z0 == 0) && (z1 == GD - 1);
            if (all) break;                      // whole grid scanned -> exact
            // min distance from p to any unscanned point (outside the cube);
            // clipped faces touch the domain boundary -> nothing beyond them
            const float INFB = 3.4e38f;
            float bd = INFB;
            if (x0 > 0)      bd = fminf(bd, px - x0 * CS);
            if (x1 < GD - 1) bd = fminf(bd, (x1 + 1) * CS - px);
            if (y0 > 0)      bd = fminf(bd, py - y0 * CS);
            if (y1 < GD - 1) bd = fminf(bd, (y1 + 1) * CS - py);
            if (z0 > 0)      bd = fminf(bd, pz - z0 * CS);
            if (z1 < GD - 1) bd = fminf(bd, (z1 + 1) * CS - pz);
            bd = fmaxf(bd - 2e-6f, 0.f);         // guard ulp mismatch vs cell calc
            if (best <= bd * bd) break;          // provably exact
        }

        float d = sqrtf(fmaxf(best, 0.f));
        sum_d = d;
        if (d < 0.005f) {
            float tt = 0.005f - d;
            pen_sum = tt * tt;
            pen_cnt = 1;
        }
        bool is_contact = false;
        #pragma unroll
        for (int j = 0; j < 10; j++) is_contact |= (h == c_contact_idx[j]);
        if (is_contact && d > 0.005f && d < 0.01f) {
            att_sum = d * d;
            att_cnt = 1;
        }
    }

    // block reduce (4 warps)
    __shared__ float s_f[3][4];
    __shared__ int   s_i[2][4];
    const unsigned FULL = 0xffffffffu;
    for (int off = 16; off > 0; off >>= 1) {
        sum_d   += __shfl_down_sync(FULL, sum_d,   off);
        pen_sum += __shfl_down_sync(FULL, pen_sum, off);
        att_sum += __shfl_down_sync(FULL, att_sum, off);
        pen_cnt += __shfl_down_sync(FULL, pen_cnt, off);
        att_cnt += __shfl_down_sync(FULL, att_cnt, off);
    }
    const int wid = t >> 5, lid = t & 31;
    if (lid == 0) {
        s_f[0][wid] = sum_d; s_f[1][wid] = pen_sum; s_f[2][wid] = att_sum;
        s_i[0][wid] = pen_cnt; s_i[1][wid] = att_cnt;
    }
    __syncthreads();

    if (t == 0) {
        float a = 0.f, c = 0.f, e = 0.f;
        int   p = 0, q = 0;
        #pragma unroll
        for (int w = 0; w < 4; w++) {
            a += s_f[0][w]; c += s_f[1][w]; e += s_f[2][w];
            p += s_i[0][w]; q += s_i[1][w];
        }
        const int slot = b * QGX + blockIdx.x;   // fixed slot -> deterministic
        g_red_f[slot * 3 + 0] = a;
        g_red_f[slot * 3 + 1] = c;
        g_red_f[slot * 3 + 2] = e;
        g_red_i[slot * 2 + 0] = p;
        g_red_i[slot * 2 + 1] = q;
        __threadfence();
        int ticket = atomicAdd(&g_ticket, 1);
        if (ticket == NQB - 1) {
            __threadfence();
            float tsum = 0.f, tpen = 0.f, tatt = 0.f;
            int   cpen = 0, catt = 0;
            #pragma unroll
            for (int r = 0; r < NQB; r++) {      // fixed order -> deterministic
                tsum += g_red_f[r * 3 + 0];
                tpen += g_red_f[r * 3 + 1];
                tatt += g_red_f[r * 3 + 2];
                cpen += g_red_i[r * 2 + 0];
                catt += g_red_i[r * 2 + 1];
            }
            float pen_loss = (cpen > 0) ? tpen / (float)cpen : 0.f;
            float att_loss = (catt > 0) ? tatt / (float)catt : 0.f;
            out[0] = 100.f * pen_loss + 10.f * att_loss;
            out[1] = pen_loss;
            out[2] = att_loss;
            out[3] = tsum / (float)NTOT;
            out[4] = (float)catt;   // num_contacts
            out[5] = (float)cpen;   // num_penetrations
            g_ticket = 0;           // self-reset for next graph replay
        }
    }
}

extern "C" void kernel_launch(void* const* d_in, const int* in_sizes, int n_in,
                              void* d_out, int out_size)
{
    const float* hand = (const float*)d_in[0];  // [8, 778, 3] f32
    const float* obj  = (const float*)d_in[1];  // [8, 40000, 3] f32
    float* out = (float*)d_out;

    dim3 pg((VOBJ + 255) / 256, B);
    count_kernel  <<<pg, 256>>>(obj);
    scan_kernel   <<<B, 1024>>>();
    scatter_kernel<<<pg, 256>>>(obj);
    query_kernel  <<<dim3(QGX, B), QBLK>>>(hand, out);
    (void)in_sizes; (void)n_in; (void)out_size;
}

// round 15
// speedup vs baseline: 3.5802x; 3.5802x over previous
#include <cuda_runtime.h>
#include <stdint.h>

#define B       8
#define NH      778
#define VOBJ    40000
#define NTOT    (B * NH)          // 6224
#define GD      16                // grid cells per axis
#define NC      (GD * GD * GD)    // 4096 cells per batch
#define CS      (0.1f / GD)       // 6.25 mm
#define INVCS   (GD / 0.1f)

#define QWARPS  8                 // warps (queries) per block
#define QBLKS   ((NTOT + QWARPS - 1) / QWARPS)   // 778 blocks

__constant__ int c_contact_idx[10] = {745, 317, 444, 556, 673, 95, 182, 234, 279, 320};

// zero-initialized at load; scan re-zeros g_cnt, finalizer resets ticket -> replay-safe
__device__ int    g_cnt[B * NC];
__device__ int    g_start[B * (NC + 1)];
__device__ int    g_fill[B * NC];
__device__ int    g_cellid[B * VOBJ];
__device__ float4 g_pts[B * VOBJ];
__device__ float  g_red_f[QBLKS * 3];
__device__ int    g_red_i[QBLKS * 2];
__device__ int    g_ticket;

__device__ __forceinline__ void cell_of(float x, float y, float z,
                                        int& cx, int& cy, int& cz) {
    cx = min(GD - 1, max(0, (int)(x * INVCS)));
    cy = min(GD - 1, max(0, (int)(y * INVCS)));
    cz = min(GD - 1, max(0, (int)(z * INVCS)));
}

// K1: histogram points into cells
__global__ __launch_bounds__(256) void count_kernel(const float* __restrict__ obj)
{
    const int j = blockIdx.x * 256 + threadIdx.x;
    const int b = blockIdx.y;
    if (j >= VOBJ) return;
    const float* p = obj + ((size_t)b * VOBJ + j) * 3;
    int cx, cy, cz;
    cell_of(p[0], p[1], p[2], cx, cy, cz);
    const int cell = (cz * GD + cy) * GD + cx;
    g_cellid[b * VOBJ + j] = cell;
    atomicAdd(&g_cnt[b * NC + cell], 1);
}

// K2: exclusive prefix sum over 4096 cells per batch, staged through smem
// (all global traffic coalesced). Re-zeros g_cnt; fills g_start + g_fill.
__global__ __launch_bounds__(256) void scan_kernel()
{
    const int b = blockIdx.x;
    const int t = threadIdx.x;
    const int lane = t & 31, wid = t >> 5;
    __shared__ int sc[NC];          // 16 KB

    // coalesced load + reset
    #pragma unroll
    for (int i = t; i < NC; i += 256) {
        sc[i] = g_cnt[b * NC + i];
        g_cnt[b * NC + i] = 0;
    }
    __syncthreads();

    // each thread owns contiguous chunk of 16 (from smem; cheap)
    int c[16], sum = 0;
    #pragma unroll
    for (int i = 0; i < 16; i++) { c[i] = sc[t * 16 + i]; sum += c[i]; }

    int incl = sum;
    #pragma unroll
    for (int off = 1; off < 32; off <<= 1) {
        int v = __shfl_up_sync(0xffffffffu, incl, off);
        if (lane >= off) incl += v;
    }
    __shared__ int wsum[8];
    if (lane == 31) wsum[wid] = incl;
    __syncthreads();
    __shared__ int wexc[8];
    if (t == 0) {
        int run = 0;
        #pragma unroll
        for (int w = 0; w < 8; w++) { wexc[w] = run; run += wsum[w]; }
    }
    __syncthreads();

    int run = wexc[wid] + (incl - sum);
    #pragma unroll
    for (int i = 0; i < 16; i++) { sc[t * 16 + i] = run; run += c[i]; }
    __syncthreads();

    // coalesced write-back
    #pragma unroll
    for (int i = t; i < NC; i += 256) {
        int v = sc[i];
        g_start[b * (NC + 1) + i] = v;
        g_fill[b * NC + i] = v;
    }
    if (t == 255) g_start[b * (NC + 1) + NC] = VOBJ;
}

// K3: scatter points into cell-sorted order
__global__ __launch_bounds__(256) void scatter_kernel(const float* __restrict__ obj)
{
    const int j = blockIdx.x * 256 + threadIdx.x;
    const int b = blockIdx.y;
    if (j >= VOBJ) return;
    const float* p = obj + ((size_t)b * VOBJ + j) * 3;
    const int cell = g_cellid[b * VOBJ + j];
    const int pos  = atomicAdd(&g_fill[b * NC + cell], 1);
    g_pts[b * VOBJ + pos] = make_float4(p[0], p[1], p[2], 0.f);
}

// K4: exact 1-NN, ONE WARP PER QUERY; fused stats + ticket finalize
__global__ __launch_bounds__(QWARPS * 32) void query_kernel(
    const float* __restrict__ hand, float* __restrict__ out)
{
    const int t    = threadIdx.x;
    const int lane = t & 31;
    const int w    = t >> 5;
    const int q    = blockIdx.x * QWARPS + w;
    const unsigned FULL = 0xffffffffu;

    float d = 0.f;
    int   h = 0, valid = 0;

    if (q < NTOT) {
        valid = 1;
        const int b = q / NH;
        h = q - b * NH;
        const float* hp = hand + ((size_t)b * NH + h) * 3;
        const float px = hp[0], py = hp[1], pz = hp[2];
        int cx, cy, cz;
        cell_of(px, py, pz, cx, cy, cz);
        const int sb = b * (NC + 1);
        const float4* pts = g_pts + (size_t)b * VOBJ;

        float best = 3.4e38f;
        for (int r = 1; r <= GD; r++) {
            const int x0 = max(0, cx - r), x1 = min(GD - 1, cx + r);
            const int y0 = max(0, cy - r), y1 = min(GD - 1, cy + r);
            const int z0 = max(0, cz - r), z1 = min(GD - 1, cz + r);
            const int ny = y1 - y0 + 1;
            const int nrows = ny * (z1 - z0 + 1);
            best = 3.4e38f;

            for (int base = 0; base < nrows; base += 32) {
                const int li = base + lane;
                int s = 0, e = 0;
                if (li < nrows) {
                    const int zz = z0 + li / ny;
                    const int yy = y0 + li % ny;
                    const int row = sb + (zz * GD + yy) * GD;
                    s = g_start[row + x0];
                    e = g_start[row + x1 + 1];   // contiguous x-run
                }
                const int cnt = min(nrows - base, 32);
                for (int rr = 0; rr < cnt; rr++) {
                    const int ss = __shfl_sync(FULL, s, rr);
                    const int ee = __shfl_sync(FULL, e, rr);
                    for (int k = ss + lane; k < ee; k += 32) {
                        float4 qq = pts[k];
                        float dx = px - qq.x, dy = py - qq.y, dz = pz - qq.z;
                        best = fminf(best, fmaf(dx, dx, fmaf(dy, dy, dz * dz)));
                    }
                }
            }
            // warp min
            #pragma unroll
            for (int off = 16; off > 0; off >>= 1)
                best = fminf(best, __shfl_xor_sync(FULL, best, off));

            const bool all = (x0 == 0) && (x1 == GD - 1) && (y0 == 0) &&
                             (y1 == GD - 1) && (z0 == 0) && (z1 == GD - 1);
            if (all) break;
            float bd = 3.4e38f;
            if (x0 > 0)      bd = fminf(bd, px - x0 * CS);
            if (x1 < GD - 1) bd = fminf(bd, (x1 + 1) * CS - px);
            if (y0 > 0)      bd = fminf(bd, py - y0 * CS);
            if (y1 < GD - 1) bd = fminf(bd, (y1 + 1) * CS - py);
            if (z0 > 0)      bd = fminf(bd, pz - z0 * CS);
            if (z1 < GD - 1) bd = fminf(bd, (z1 + 1) * CS - pz);
            bd = fmaxf(bd - 2e-6f, 0.f);
            if (best <= bd * bd) break;          // provably exact
        }
        d = sqrtf(fmaxf(best, 0.f));
    }

    // per-warp stats (lane 0), then cross-warp combine via smem
    __shared__ float sf[3][QWARPS];
    __shared__ int   si[2][QWARPS];
    if (lane == 0) {
        float sum_d = 0.f, pen = 0.f, att = 0.f;
        int   pc = 0, ac = 0;
        if (valid) {
            sum_d = d;
            if (d < 0.005f) { float tt = 0.005f - d; pen = tt * tt; pc = 1; }
            bool isc = false;
            #pragma unroll
            for (int j = 0; j < 10; j++) isc |= (h == c_contact_idx[j]);
            if (isc && d > 0.005f && d < 0.01f) { att = d * d; ac = 1; }
        }
        sf[0][w] = sum_d; sf[1][w] = pen; sf[2][w] = att;
        si[0][w] = pc;    si[1][w] = ac;
    }
    __syncthreads();

    __shared__ int s_last;
    if (t == 0) {
        float a = 0.f, c = 0.f, e = 0.f;
        int   p = 0, qq = 0;
        #pragma unroll
        for (int i = 0; i < QWARPS; i++) {
            a += sf[0][i]; c += sf[1][i]; e += sf[2][i];
            p += si[0][i]; qq += si[1][i];
        }
        g_red_f[blockIdx.x * 3 + 0] = a;
        g_red_f[blockIdx.x * 3 + 1] = c;
        g_red_f[blockIdx.x * 3 + 2] = e;
        g_red_i[blockIdx.x * 2 + 0] = p;
        g_red_i[blockIdx.x * 2 + 1] = qq;
        __threadfence();
        int ticket = atomicAdd(&g_ticket, 1);
        s_last = (ticket == QBLKS - 1) ? 1 : 0;
    }
    __syncthreads();
    if (!s_last) return;
    __threadfence();

    // finalizer block: combine 778 slots with 256 threads, fixed order
    float a = 0.f, c = 0.f, e = 0.f;
    int   p = 0, qq = 0;
    for (int r = t; r < QBLKS; r += QWARPS * 32) {
        a += g_red_f[r * 3 + 0];
        c += g_red_f[r * 3 + 1];
        e += g_red_f[r * 3 + 2];
        p += g_red_i[r * 2 + 0];
        qq += g_red_i[r * 2 + 1];
    }
    #pragma unroll
    for (int off = 16; off > 0; off >>= 1) {
        a += __shfl_down_sync(FULL, a, off);
        c += __shfl_down_sync(FULL, c, off);
        e += __shfl_down_sync(FULL, e, off);
        p += __shfl_down_sync(FULL, p, off);
        qq += __shfl_down_sync(FULL, qq, off);
    }
    __shared__ float ff[3][QWARPS];
    __shared__ int   ii[2][QWARPS];
    if (lane == 0) {
        ff[0][w] = a; ff[1][w] = c; ff[2][w] = e;
        ii[0][w] = p; ii[1][w] = qq;
    }
    __syncthreads();
    if (t == 0) {
        float ta = 0.f, tc = 0.f, te = 0.f;
        int   tp = 0, tq = 0;
        #pragma unroll
        for (int i = 0; i < QWARPS; i++) {
            ta += ff[0][i]; tc += ff[1][i]; te += ff[2][i];
            tp += ii[0][i]; tq += ii[1][i];
        }
        float pen_loss = (tp > 0) ? tc / (float)tp : 0.f;
        float att_loss = (tq > 0) ? te / (float)tq : 0.f;
        out[0] = 100.f * pen_loss + 10.f * att_loss;
        out[1] = pen_loss;
        out[2] = att_loss;
        out[3] = ta / (float)NTOT;
        out[4] = (float)tq;   // num_contacts
        out[5] = (float)tp;   // num_penetrations
        g_ticket = 0;         // self-reset for next graph replay
    }
}

extern "C" void kernel_launch(void* const* d_in, const int* in_sizes, int n_in,
                              void* d_out, int out_size)
{
    const float* hand = (const float*)d_in[0];  // [8, 778, 3] f32
    const float* obj  = (const float*)d_in[1];  // [8, 40000, 3] f32
    float* out = (float*)d_out;

    dim3 pg((VOBJ + 255) / 256, B);
    count_kernel  <<<pg, 256>>>(obj);
    scan_kernel   <<<B, 256>>>();
    scatter_kernel<<<pg, 256>>>(obj);
    query_kernel  <<<QBLKS, QWARPS * 32>>>(hand, out);
    (void)in_sizes; (void)n_in; (void)out_size;
}

// round 16
// speedup vs baseline: 3.7594x; 1.0500x over previous
#include <cuda_runtime.h>
#include <stdint.h>

#define B       8
#define NH      778
#define VOBJ    40000
#define NTOT    (B * NH)          // 6224
#define GD      16                // grid cells per axis
#define NC      (GD * GD * GD)    // 4096 cells per batch
#define CS      (0.1f / GD)       // 6.25 mm
#define INVCS   (GD / 0.1f)

#define QWARPS  8                 // warps (queries) per block
#define QBX     ((NH + QWARPS - 1) / QWARPS)   // 98 x-blocks per batch
#define NQB     (QBX * B)                      // 784 stat slots

__constant__ int c_contact_idx[10] = {745, 317, 444, 556, 673, 95, 182, 234, 279, 320};

// zero-initialized at load; scan re-zeros g_cnt, finalizer resets ticket -> replay-safe
__device__ int    g_cnt[B * NC];
__device__ int    g_start[B * (NC + 1)];
__device__ int    g_fill[B * NC];
__device__ int    g_cellid[B * VOBJ];
__device__ float4 g_pts[B * VOBJ];
__device__ float  g_red_f[NQB * 3];
__device__ int    g_red_i[NQB * 2];
__device__ int    g_ticket;

__device__ __forceinline__ void cell_of(float x, float y, float z,
                                        int& cx, int& cy, int& cz) {
    cx = min(GD - 1, max(0, (int)(x * INVCS)));
    cy = min(GD - 1, max(0, (int)(y * INVCS)));
    cz = min(GD - 1, max(0, (int)(z * INVCS)));
}

// K1: histogram points into cells
__global__ __launch_bounds__(256) void count_kernel(const float* __restrict__ obj)
{
    const int j = blockIdx.x * 256 + threadIdx.x;
    const int b = blockIdx.y;
    if (j >= VOBJ) return;
    const float* p = obj + ((size_t)b * VOBJ + j) * 3;
    int cx, cy, cz;
    cell_of(p[0], p[1], p[2], cx, cy, cz);
    const int cell = (cz * GD + cy) * GD + cx;
    g_cellid[b * VOBJ + j] = cell;
    atomicAdd(&g_cnt[b * NC + cell], 1);
}

// K2: exclusive prefix sum over 4096 cells per batch, staged through smem.
// Re-zeros g_cnt; fills g_start + g_fill.
__global__ __launch_bounds__(256) void scan_kernel()
{
    const int b = blockIdx.x;
    const int t = threadIdx.x;
    const int lane = t & 31, wid = t >> 5;
    __shared__ int sc[NC];          // 16 KB

    #pragma unroll
    for (int i = t; i < NC; i += 256) {
        sc[i] = g_cnt[b * NC + i];
        g_cnt[b * NC + i] = 0;
    }
    __syncthreads();

    int c[16], sum = 0;
    #pragma unroll
    for (int i = 0; i < 16; i++) { c[i] = sc[t * 16 + i]; sum += c[i]; }

    int incl = sum;
    #pragma unroll
    for (int off = 1; off < 32; off <<= 1) {
        int v = __shfl_up_sync(0xffffffffu, incl, off);
        if (lane >= off) incl += v;
    }
    __shared__ int wsum[8];
    if (lane == 31) wsum[wid] = incl;
    __syncthreads();
    __shared__ int wexc[8];
    if (t == 0) {
        int run = 0;
        #pragma unroll
        for (int w = 0; w < 8; w++) { wexc[w] = run; run += wsum[w]; }
    }
    __syncthreads();

    int run = wexc[wid] + (incl - sum);
    #pragma unroll
    for (int i = 0; i < 16; i++) { sc[t * 16 + i] = run; run += c[i]; }
    __syncthreads();

    #pragma unroll
    for (int i = t; i < NC; i += 256) {
        int v = sc[i];
        g_start[b * (NC + 1) + i] = v;
        g_fill[b * NC + i] = v;
    }
    if (t == 255) g_start[b * (NC + 1) + NC] = VOBJ;
}

// K3: scatter points into cell-sorted order
__global__ __launch_bounds__(256) void scatter_kernel(const float* __restrict__ obj)
{
    const int j = blockIdx.x * 256 + threadIdx.x;
    const int b = blockIdx.y;
    if (j >= VOBJ) return;
    const float* p = obj + ((size_t)b * VOBJ + j) * 3;
    const int cell = g_cellid[b * VOBJ + j];
    const int pos  = atomicAdd(&g_fill[b * NC + cell], 1);
    g_pts[b * VOBJ + pos] = make_float4(p[0], p[1], p[2], 0.f);
}

// K4: exact 1-NN, one warp per query; center-cell seed + pruned r=1 scan
__global__ __launch_bounds__(QWARPS * 32) void query_kernel(
    const float* __restrict__ hand, float* __restrict__ out)
{
    const int t    = threadIdx.x;
    const int lane = t & 31;
    const int w    = t >> 5;
    const int b    = blockIdx.y;
    const int h    = blockIdx.x * QWARPS + w;
    const unsigned FULL = 0xffffffffu;

    float d = 0.f;

    if (h < NH) {
        const float* hp = hand + ((size_t)b * NH + h) * 3;
        const float px = hp[0], py = hp[1], pz = hp[2];
        int cx, cy, cz;
        cell_of(px, py, pz, cx, cy, cz);
        const int sb = b * (NC + 1);
        const float4* pts = g_pts + (size_t)b * VOBJ;

        // ---- center-cell seed pass ----
        float best = 3.4e38f;
        {
            const int crow = sb + (cz * GD + cy) * GD + cx;
            const int s0 = g_start[crow];        // same addr all lanes -> broadcast
            const int e0 = g_start[crow + 1];
            for (int k = s0 + lane; k < e0; k += 32) {
                float4 qq = pts[k];
                float dx = px - qq.x, dy = py - qq.y, dz = pz - qq.z;
                best = fminf(best, fmaf(dx, dx, fmaf(dy, dy, dz * dz)));
            }
            #pragma unroll
            for (int off = 16; off > 0; off >>= 1)
                best = fminf(best, __shfl_xor_sync(FULL, best, off));
        }

        for (int r = 1; r <= GD; r++) {
            const int x0 = max(0, cx - r), x1 = min(GD - 1, cx + r);
            const int y0 = max(0, cy - r), y1 = min(GD - 1, cy + r);
            const int z0 = max(0, cz - r), z1 = min(GD - 1, cz + r);
            const int ny = y1 - y0 + 1;
            const int nrows = ny * (z1 - z0 + 1);
            if (r > 1) best = 3.4e38f;          // full rescan (superset) at r>=2

            const float lim = best * 1.0001f + 1e-12f;   // prune radius^2 (+margin)

            for (int base = 0; base < nrows; base += 32) {
                const int li = base + lane;
                int s = 0, e = 0;
                if (li < nrows) {
                    const int zz = z0 + li / ny;
                    const int yy = y0 + li % ny;
                    const int row = sb + (zz * GD + yy) * GD;
                    int xs = x0, xe = x1;
                    if (r == 1) {
                        // row box distance in y,z
                        float ry0 = yy * CS, rz0 = zz * CS;
                        float dy = fmaxf(fmaxf(ry0 - py, py - (ry0 + CS)), 0.f);
                        float dz = fmaxf(fmaxf(rz0 - pz, pz - (rz0 + CS)), 0.f);
                        float rem = lim - fmaf(dy, dy, dz * dz);
                        if (rem < 0.f) { xs = 1; xe = 0; }      // whole row pruned
                        else {
                            if (x0 < cx) {                       // left cell
                                float dx = px - cx * CS;
                                if (dx * dx > rem) xs = cx;
                            }
                            if (x1 > cx) {                       // right cell
                                float dx = (cx + 1) * CS - px;
                                if (dx * dx > rem) xe = cx;
                            }
                        }
                    }
                    if (xs <= xe) {
                        s = g_start[row + xs];
                        e = g_start[row + xe + 1];               // contiguous x-run
                    }
                }
                const int cnt = min(nrows - base, 32);
                for (int rr = 0; rr < cnt; rr++) {
                    const int ss = __shfl_sync(FULL, s, rr);
                    const int ee = __shfl_sync(FULL, e, rr);
                    if (ss >= ee) continue;                      // pruned/empty row
                    for (int k = ss + lane; k < ee; k += 32) {
                        float4 qq = pts[k];
                        float dx = px - qq.x, dy = py - qq.y, dz = pz - qq.z;
                        best = fminf(best, fmaf(dx, dx, fmaf(dy, dy, dz * dz)));
                    }
                }
            }
            #pragma unroll
            for (int off = 16; off > 0; off >>= 1)
                best = fminf(best, __shfl_xor_sync(FULL, best, off));

            const bool all = (x0 == 0) && (x1 == GD - 1) && (y0 == 0) &&
                             (y1 == GD - 1) && (z0 == 0) && (z1 == GD - 1);
            if (all) break;
            float bd = 3.4e38f;
            if (x0 > 0)      bd = fminf(bd, px - x0 * CS);
            if (x1 < GD - 1) bd = fminf(bd, (x1 + 1) * CS - px);
            if (y0 > 0)      bd = fminf(bd, py - y0 * CS);
            if (y1 < GD - 1) bd = fminf(bd, (y1 + 1) * CS - py);
            if (z0 > 0)      bd = fminf(bd, pz - z0 * CS);
            if (z1 < GD - 1) bd = fminf(bd, (z1 + 1) * CS - pz);
            bd = fmaxf(bd - 2e-6f, 0.f);
            if (best <= bd * bd) break;          // provably exact
        }
        d = sqrtf(fmaxf(best, 0.f));
    }

    // per-warp stats, cross-warp combine, ticket finalize
    __shared__ float sf[3][QWARPS];
    __shared__ int   si[2][QWARPS];
    if (lane == 0) {
        float sum_d = 0.f, pen = 0.f, att = 0.f;
        int   pc = 0, ac = 0;
        if (h < NH) {
            sum_d = d;
            if (d < 0.005f) { float tt = 0.005f - d; pen = tt * tt; pc = 1; }
            bool isc = false;
            #pragma unroll
            for (int j = 0; j < 10; j++) isc |= (h == c_contact_idx[j]);
            if (isc && d > 0.005f && d < 0.01f) { att = d * d; ac = 1; }
        }
        sf[0][w] = sum_d; sf[1][w] = pen; sf[2][w] = att;
        si[0][w] = pc;    si[1][w] = ac;
    }
    __syncthreads();

    __shared__ int s_last;
    if (t == 0) {
        float a = 0.f, c = 0.f, e = 0.f;
        int   p = 0, qq = 0;
        #pragma unroll
        for (int i = 0; i < QWARPS; i++) {
            a += sf[0][i]; c += sf[1][i]; e += sf[2][i];
            p += si[0][i]; qq += si[1][i];
        }
        const int slot = b * QBX + blockIdx.x;
        g_red_f[slot * 3 + 0] = a;
        g_red_f[slot * 3 + 1] = c;
        g_red_f[slot * 3 + 2] = e;
        g_red_i[slot * 2 + 0] = p;
        g_red_i[slot * 2 + 1] = qq;
        __threadfence();
        int ticket = atomicAdd(&g_ticket, 1);
        s_last = (ticket == NQB - 1) ? 1 : 0;
    }
    __syncthreads();
    if (!s_last) return;
    __threadfence();

    float a = 0.f, c = 0.f, e = 0.f;
    int   p = 0, qq = 0;
    for (int r = t; r < NQB; r += QWARPS * 32) {   // fixed order -> deterministic
        a += g_red_f[r * 3 + 0];
        c += g_red_f[r * 3 + 1];
        e += g_red_f[r * 3 + 2];
        p += g_red_i[r * 2 + 0];
        qq += g_red_i[r * 2 + 1];
    }
    #pragma unroll
    for (int off = 16; off > 0; off >>= 1) {
        a += __shfl_down_sync(FULL, a, off);
        c += __shfl_down_sync(FULL, c, off);
        e += __shfl_down_sync(FULL, e, off);
        p += __shfl_down_sync(FULL, p, off);
        qq += __shfl_down_sync(FULL, qq, off);
    }
    __shared__ float ff[3][QWARPS];
    __shared__ int   ii[2][QWARPS];
    if (lane == 0) {
        ff[0][w] = a; ff[1][w] = c; ff[2][w] = e;
        ii[0][w] = p; ii[1][w] = qq;
    }
    __syncthreads();
    if (t == 0) {
        float ta = 0.f, tc = 0.f, te = 0.f;
        int   tp = 0, tq = 0;
        #pragma unroll
        for (int i = 0; i < QWARPS; i++) {
            ta += ff[0][i]; tc += ff[1][i]; te += ff[2][i];
            tp += ii[0][i]; tq += ii[1][i];
        }
        float pen_loss = (tp > 0) ? tc / (float)tp : 0.f;
        float att_loss = (tq > 0) ? te / (float)tq : 0.f;
        out[0] = 100.f * pen_loss + 10.f * att_loss;
        out[1] = pen_loss;
        out[2] = att_loss;
        out[3] = ta / (float)NTOT;
        out[4] = (float)tq;   // num_contacts
        out[5] = (float)tp;   // num_penetrations
        g_ticket = 0;         // self-reset for next graph replay
    }
}

extern "C" void kernel_launch(void* const* d_in, const int* in_sizes, int n_in,
                              void* d_out, int out_size)
{
    const float* hand = (const float*)d_in[0];  // [8, 778, 3] f32
    const float* obj  = (const float*)d_in[1];  // [8, 40000, 3] f32
    float* out = (float*)d_out;

    dim3 pg((VOBJ + 255) / 256, B);
    count_kernel  <<<pg, 256>>>(obj);
    scan_kernel   <<<B, 256>>>();
    scatter_kernel<<<pg, 256>>>(obj);
    query_kernel  <<<dim3(QBX, B), QWARPS * 32>>>(hand, out);
    (void)in_sizes; (void)n_in; (void)out_size;
}